// round 5
// baseline (speedup 1.0000x reference)
#include <cuda_runtime.h>
#include <cuda_bf16.h>

// PointMatcher: pred (N,20,2) f32, gt (M,20,2) f32.
// distances(i,j) = mean_p sqrt((pred[i,p]-gt[j,p])^2 summed over xy)
// out = [ matched_points (N*40) | confidence (N) | indices-as-float (N) ]

#define P_PTS   20
#define ROW_F   (P_PTS * 2)      // 40 floats per row
#define TI      4                // preds per block
#define TILE_J  256              // gt rows per smem tile
#define NTHREADS 256

__device__ __forceinline__ float fsqrt_approx(float x) {
    float r;
    asm("sqrt.approx.f32 %0, %1;" : "=f"(r) : "f"(x));
    return r;
}

__global__ __launch_bounds__(NTHREADS, 1)
void PointMatcher_kernel(const float* __restrict__ pred,
                         const float* __restrict__ gt,
                         float* __restrict__ out,
                         int N, int M)
{
    __shared__ float2 tileT[P_PTS][TILE_J + 1];   // transposed gt tile, padded
    __shared__ float  red_m[TI][NTHREADS / 32];
    __shared__ int    red_i[TI][NTHREADS / 32];
    __shared__ float  best_m[TI];
    __shared__ int    best_i[TI];

    const int tid  = threadIdx.x;
    const int lane = tid & 31;
    const int warp = tid >> 5;
    const int i0   = blockIdx.x * TI;             // first pred row of this block

    // ---- load TI pred rows into registers (broadcast across threads) ----
    float pr[TI][ROW_F];
    #pragma unroll
    for (int i = 0; i < TI; i++) {
        int row = i0 + i;
        if (row >= N) row = N - 1;                // safe clamp (N % TI == 0 normally)
        const float4* p4 = reinterpret_cast<const float4*>(pred + (size_t)row * ROW_F);
        #pragma unroll
        for (int k = 0; k < ROW_F / 4; k++) {
            float4 v = __ldg(p4 + k);
            pr[i][k * 4 + 0] = v.x;
            pr[i][k * 4 + 1] = v.y;
            pr[i][k * 4 + 2] = v.z;
            pr[i][k * 4 + 3] = v.w;
        }
    }

    float mn[TI];
    int   mi[TI];
    #pragma unroll
    for (int i = 0; i < TI; i++) { mn[i] = 3.4e38f; mi[i] = 0; }

    const int numTiles = (M + TILE_J - 1) / TILE_J;

    for (int t = 0; t < numTiles; t++) {
        const int jBase = t * TILE_J;

        // ---- stage gt tile into smem, transposed to [p][j] float2 ----
        // tile holds TILE_J rows * 40 floats = TILE_J*10 float4s
        {
            const int nf4 = TILE_J * (ROW_F / 4);
            const float4* g4 = reinterpret_cast<const float4*>(gt + (size_t)jBase * ROW_F);
            #pragma unroll
            for (int k = 0; k < nf4 / NTHREADS; k++) {
                int lin4 = tid + k * NTHREADS;           // [0, 2560)
                int jl   = lin4 / (ROW_F / 4);           // local row
                int c4   = lin4 % (ROW_F / 4);           // which float4 in row
                if (jBase + jl < M) {
                    float4 v = __ldg(g4 + lin4);
                    tileT[c4 * 2 + 0][jl] = make_float2(v.x, v.y);
                    tileT[c4 * 2 + 1][jl] = make_float2(v.z, v.w);
                } else {
                    tileT[c4 * 2 + 0][jl] = make_float2(1e30f, 1e30f);
                    tileT[c4 * 2 + 1][jl] = make_float2(1e30f, 1e30f);
                }
            }
        }
        __syncthreads();

        // ---- compute: this thread owns gt row j = jBase + tid ----
        const int jg = jBase + tid;
        if (jg < M) {
            float s[TI];
            #pragma unroll
            for (int i = 0; i < TI; i++) s[i] = 0.0f;

            #pragma unroll
            for (int p = 0; p < P_PTS; p++) {
                float2 g = tileT[p][tid];
                #pragma unroll
                for (int i = 0; i < TI; i++) {
                    float dx = pr[i][2 * p + 0] - g.x;
                    float dy = pr[i][2 * p + 1] - g.y;
                    float d2 = fmaf(dy, dy, dx * dx);
                    s[i] += fsqrt_approx(d2);
                }
            }
            #pragma unroll
            for (int i = 0; i < TI; i++) {
                float d = s[i] * (1.0f / P_PTS);
                if (d < mn[i]) { mn[i] = d; mi[i] = jg; }
            }
        }
        __syncthreads();
    }

    // ---- reduction: warp-level min+argmin (tie -> lower index) ----
    #pragma unroll
    for (int i = 0; i < TI; i++) {
        float m = mn[i];
        int   j = mi[i];
        #pragma unroll
        for (int off = 16; off > 0; off >>= 1) {
            float m2 = __shfl_down_sync(0xFFFFFFFFu, m, off);
            int   j2 = __shfl_down_sync(0xFFFFFFFFu, j, off);
            if (m2 < m || (m2 == m && j2 < j)) { m = m2; j = j2; }
        }
        if (lane == 0) { red_m[i][warp] = m; red_i[i][warp] = j; }
    }
    __syncthreads();

    if (tid < TI) {
        float m = red_m[tid][0];
        int   j = red_i[tid][0];
        #pragma unroll
        for (int w = 1; w < NTHREADS / 32; w++) {
            float m2 = red_m[tid][w];
            int   j2 = red_i[tid][w];
            if (m2 < m || (m2 == m && j2 < j)) { m = m2; j = j2; }
        }
        best_m[tid] = m;
        best_i[tid] = j;
    }
    __syncthreads();

    // ---- write outputs ----
    // matched_points: 4 rows * 40 floats = 160 elements
    if (tid < TI * ROW_F) {
        int i = tid / ROW_F;
        int c = tid % ROW_F;
        if (i0 + i < N)
            out[(size_t)(i0 + i) * ROW_F + c] = __ldg(gt + (size_t)best_i[i] * ROW_F + c);
    }
    if (tid < TI) {
        int row = i0 + tid;
        if (row < N) {
            float m    = best_m[tid];
            float conf = (m > 2.0f) ? 0.0f : __expf(-m);
            out[(size_t)N * ROW_F + row]     = conf;                 // confidence
            out[(size_t)N * ROW_F + N + row] = (float)best_i[tid];   // index as float
        }
    }
}

extern "C" void kernel_launch(void* const* d_in, const int* in_sizes, int n_in,
                              void* d_out, int out_size) {
    const float* pred = (const float*)d_in[0];
    const float* gt   = (const float*)d_in[1];
    float*       out  = (float*)d_out;

    const int N = in_sizes[0] / ROW_F;   // 1024
    const int M = in_sizes[1] / ROW_F;   // 2048

    const int blocks = (N + TI - 1) / TI;
    PointMatcher_kernel<<<blocks, NTHREADS>>>(pred, gt, out, N, M);
}